// round 4
// baseline (speedup 1.0000x reference)
#include <cuda_runtime.h>
#include <math.h>

#define Nn   50000
#define Ee   500000
#define SDv  128
#define HIDv 64
#define K1v  257
#define M3v  134
#define M3P  136
#define TILE 64
#define TEP  65
#define NT   256
#define NTILES_E ((Ee + TILE - 1) / TILE)
#define NTILES_N ((Nn + TILE - 1) / TILE)

// ---- edge-kernel shared memory (float offsets); H2 reuses H1 ----
#define OW2 0
#define OB2 (OW2 + HIDv*HIDv)          // 4096
#define OW3 (OB2 + HIDv)               // 4160
#define OB3 (OW3 + HIDv*M3P)           // 12864
#define OWD (OB3 + M3P)                // 13000
#define OB1 (OWD + HIDv)               // 13064
#define OH1 (OB1 + HIDv)               // 13128 (64 x 65)
#define OMD (OH1 + HIDv*TEP)           // 17288
#define OMS (OMD + TILE)
#define OMC (OMS + TILE)
#define ODD (OMC + TILE)
#define OGV (ODD + TILE)
#define SME_FLOATS (OGV + 6*TILE)      // 17928
#define SME_BYTES (SME_FLOATS * 4)     // 71712 B -> 3 CTAs/SM

// ---- PQ precompute kernel smem ----
#define OWpq 0
#define OXpq (OWpq + 128*128)
#define SMP_FLOATS (OXpq + SDv*TEP)
#define SMP_BYTES (SMP_FLOATS * 4)     // ~99 KB -> 2 CTAs/SM

// ---- node kernel: 32-node tiles, two-pass K, Wn2 from global ----
#define NTILE 32
#define NTP   33
#define OWn1 0
#define OBn1 (OWn1 + 2*SDv*HIDv)       // 16384
#define OX2  (OBn1 + HIDv)             // 16448 (128 x 33)
#define OU2  (OX2 + SDv*NTP)           // 20672 (64 x 33)
#define SMN_FLOATS (OU2 + HIDv*NTP)    // 22784
#define SMN_BYTES (SMN_FLOATS * 4)     // 91136 B -> 2 CTAs/SM
#define NTILES_N2 ((Nn + NTILE - 1) / NTILE)

__device__ float g_s[(size_t)Nn * SDv];
__device__ float g_v[(size_t)Nn * 9];
__device__ float g_sagg[(size_t)Nn * SDv];
__device__ float g_vagg[(size_t)Nn * 9];
__device__ float g_pq[(size_t)Nn * 128];
__device__ float g_cnt[Nn];
__device__ float g_inv[Nn];

typedef unsigned long long u64;

__device__ __forceinline__ float silu_f(float x) { return x / (1.0f + __expf(-x)); }

__device__ __forceinline__ void red4(float* p, float a, float b, float c, float d) {
    asm volatile("red.global.add.v4.f32 [%0], {%1,%2,%3,%4};"
                 :: "l"(p), "f"(a), "f"(b), "f"(c), "f"(d) : "memory");
}
__device__ __forceinline__ u64 splat2(float a) {
    u64 r; asm("mov.b64 %0, {%1, %1};" : "=l"(r) : "f"(a)); return r;
}
__device__ __forceinline__ void ffma2(u64& acc, u64 a2, u64 w2) {
    asm("fma.rn.f32x2 %0, %1, %2, %0;" : "+l"(acc) : "l"(a2), "l"(w2));
}
__device__ __forceinline__ void unpack2(u64 p, float& lo, float& hi) {
    asm("mov.b64 {%0, %1}, %2;" : "=f"(lo), "=f"(hi) : "l"(p));
}

// -------------------- init / misc --------------------
__global__ void k_init(const float* __restrict__ s, const float* __restrict__ v) {
    int i = blockIdx.x * blockDim.x + threadIdx.x;
    if (i < Nn * SDv) g_s[i] = s[i];
    if (i < Nn * 9)   g_v[i] = v[i];
    if (i < Nn)       g_cnt[i] = 0.0f;
}
__global__ void k_count(const int* __restrict__ dst) {
    int e = blockIdx.x * blockDim.x + threadIdx.x;
    if (e < Ee) atomicAdd(&g_cnt[dst[e]], 1.0f);
}
__global__ void k_inv() {
    int i = blockIdx.x * blockDim.x + threadIdx.x;
    if (i < Nn) g_inv[i] = 1.0f / fmaxf(g_cnt[i], 1.0f);
}
__global__ void k_out(float* __restrict__ out) {
    int i = blockIdx.x * blockDim.x + threadIdx.x;
    if (i < Nn * SDv) out[i] = g_s[i];
    if (i < Nn * 9)   out[(size_t)Nn * SDv + i] = g_v[i];
}

// -------------------- PQ precompute (+ zero agg) --------------------
__global__ void __launch_bounds__(NT, 2)
k_pq(const float* __restrict__ W1g, int l)
{
    extern __shared__ float sm[];
    const int tid = threadIdx.x;
    const int w = tid >> 5, lane = tid & 31;
    const float* W1 = W1g + (size_t)l * K1v * HIDv;

    for (int i = blockIdx.x * NT + tid; i < Nn * SDv; i += gridDim.x * NT) g_sagg[i] = 0.0f;
    for (int i = blockIdx.x * NT + tid; i < Nn * 9; i += gridDim.x * NT) g_vagg[i] = 0.0f;

    for (int i = tid; i < 128 * 128; i += NT) {
        int k = i >> 7, c = i & 127;
        sm[OWpq + i] = (c < 64) ? W1[k * 64 + c] : W1[(128 + k) * 64 + (c - 64)];
    }
    __syncthreads();

    for (int tile = blockIdx.x; tile < NTILES_N; tile += gridDim.x) {
        const int n0 = tile * TILE;
        const int nn = min(TILE, Nn - n0);

        for (int i = tid; i < TILE * SDv; i += NT) {
            int n = i >> 7, k = i & 127;
            sm[OXpq + k * TEP + n] = (n < nn) ? g_s[(size_t)(n0 + n) * SDv + k] : 0.0f;
        }
        __syncthreads();

        {
            u64 p0[8], p1[8];
            #pragma unroll
            for (int j = 0; j < 8; ++j) { p0[j] = 0ull; p1[j] = 0ull; }
            const int cb = 16 * w;
            #pragma unroll 2
            for (int k = 0; k < 128; ++k) {
                u64 A0 = splat2(sm[OXpq + k * TEP + lane]);
                u64 A1 = splat2(sm[OXpq + k * TEP + lane + 32]);
                const ulonglong2* wr = (const ulonglong2*)&sm[OWpq + k * 128 + cb];
                ulonglong2 w0 = wr[0], w1 = wr[1], w2 = wr[2], w3 = wr[3];
                ffma2(p0[0], A0, w0.x); ffma2(p0[1], A0, w0.y);
                ffma2(p0[2], A0, w1.x); ffma2(p0[3], A0, w1.y);
                ffma2(p0[4], A0, w2.x); ffma2(p0[5], A0, w2.y);
                ffma2(p0[6], A0, w3.x); ffma2(p0[7], A0, w3.y);
                ffma2(p1[0], A1, w0.x); ffma2(p1[1], A1, w0.y);
                ffma2(p1[2], A1, w1.x); ffma2(p1[3], A1, w1.y);
                ffma2(p1[4], A1, w2.x); ffma2(p1[5], A1, w2.y);
                ffma2(p1[6], A1, w3.x); ffma2(p1[7], A1, w3.y);
            }
            if (lane < nn) {
                float* op = &g_pq[(size_t)(n0 + lane) * 128 + cb];
                #pragma unroll
                for (int j = 0; j < 8; ++j) { float lo, hi; unpack2(p0[j], lo, hi); op[2*j] = lo; op[2*j+1] = hi; }
            }
            if (lane + 32 < nn) {
                float* op = &g_pq[(size_t)(n0 + lane + 32) * 128 + cb];
                #pragma unroll
                for (int j = 0; j < 8; ++j) { float lo, hi; unpack2(p1[j], lo, hi); op[2*j] = lo; op[2*j+1] = hi; }
            }
        }
        __syncthreads();
    }
}

// -------------------- fused edge kernel (3 CTAs/SM) --------------------
__global__ void __launch_bounds__(NT, 3)
k_edge(const int* __restrict__ dst, const int* __restrict__ src,
       const float* __restrict__ dv, const float* __restrict__ rv,
       const float* __restrict__ W1g, const float* __restrict__ b1g,
       const float* __restrict__ W2g, const float* __restrict__ b2g,
       const float* __restrict__ W3g, const float* __restrict__ b3g,
       int l)
{
    extern __shared__ float sm[];
    const int tid = threadIdx.x;
    const int w = tid >> 5, lane = tid & 31;

    const float* W1 = W1g + (size_t)l * K1v * HIDv;
    const float* b1 = b1g + l * HIDv;
    const float* W2 = W2g + l * HIDv * HIDv;
    const float* b2 = b2g + l * HIDv;
    const float* W3 = W3g + l * HIDv * M3v;
    const float* b3 = b3g + l * M3v;

    for (int i = tid; i < HIDv * HIDv; i += NT) sm[OW2 + i] = W2[i];
    for (int i = tid; i < HIDv * M3v; i += NT) {
        int k = i / M3v, c = i - k * M3v;
        sm[OW3 + k * M3P + c] = W3[i];
    }
    for (int i = tid; i < M3v; i += NT) sm[OB3 + i] = b3[i];
    for (int i = tid; i < HIDv; i += NT) {
        sm[OB2 + i] = b2[i];
        sm[OB1 + i] = b1[i];
        sm[OWD + i] = W1[256 * 64 + i];
    }
    __syncthreads();

    int*   dstS = (int*)&sm[OMD];
    int*   srcS = (int*)&sm[OMS];
    float* Cs   = &sm[OMC];
    float* dds  = &sm[ODD];
    float* gvg  = &sm[OGV];

    for (int tile = blockIdx.x; tile < NTILES_E; tile += gridDim.x) {
        const int e0 = tile * TILE;
        const int ne = min(TILE, Ee - e0);

        if (tid < TILE) {
            if (tid < ne) {
                dstS[tid] = dst[e0 + tid];
                srcS[tid] = src[e0 + tid];
                float dd = dv[e0 + tid];
                dds[tid] = dd;
                Cs[tid] = (dd < 5.0f) ? 0.5f * (cosf(0.62831853071795864769f * dd) + 1.0f) : 0.0f;
            } else {
                dstS[tid] = 0; srcS[tid] = 0; Cs[tid] = 0.0f; dds[tid] = 0.0f;
            }
        }
        __syncthreads();

        // h1[e] = silu(P[dst] + Q[src] + d*wd + b1)  -> k-major smem
        {
            const int ebase = w * 8;
            float wd0 = sm[OWD + lane], wd1 = sm[OWD + lane + 32];
            float bb0 = sm[OB1 + lane], bb1 = sm[OB1 + lane + 32];
            for (int q = 0; q < 8; ++q) {
                int ee = ebase + q;
                if (ee < ne) {
                    const float* pp = &g_pq[(size_t)dstS[ee] * 128];
                    const float* qq = &g_pq[(size_t)srcS[ee] * 128 + 64];
                    float de = dds[ee];
                    float h0  = pp[lane]      + qq[lane]      + de * wd0 + bb0;
                    float h1v = pp[lane + 32] + qq[lane + 32] + de * wd1 + bb1;
                    sm[OH1 + lane * TEP + ee]        = silu_f(h0);
                    sm[OH1 + (lane + 32) * TEP + ee] = silu_f(h1v);
                } else {
                    sm[OH1 + lane * TEP + ee]        = 0.0f;
                    sm[OH1 + (lane + 32) * TEP + ee] = 0.0f;
                }
            }
        }
        __syncthreads();

        // ---- GEMM2: h2 = silu(h1 @ W2 + b2); result overwrites H1 ----
        {
            u64 p0[4], p1[4];
            #pragma unroll
            for (int j = 0; j < 4; ++j) { p0[j] = 0ull; p1[j] = 0ull; }
            const int cb = 8 * w;
            #pragma unroll 4
            for (int k = 0; k < HIDv; ++k) {
                u64 A0 = splat2(sm[OH1 + k * TEP + lane]);
                u64 A1 = splat2(sm[OH1 + k * TEP + lane + 32]);
                const ulonglong2* wr = (const ulonglong2*)&sm[OW2 + k * HIDv + cb];
                ulonglong2 w0 = wr[0], w1 = wr[1];
                ffma2(p0[0], A0, w0.x); ffma2(p0[1], A0, w0.y);
                ffma2(p0[2], A0, w1.x); ffma2(p0[3], A0, w1.y);
                ffma2(p1[0], A1, w0.x); ffma2(p1[1], A1, w0.y);
                ffma2(p1[2], A1, w1.x); ffma2(p1[3], A1, w1.y);
            }
            __syncthreads();  // all reads of h1 complete before overwrite
            #pragma unroll
            for (int j = 0; j < 4; ++j) {
                float l0, h0, l1, h1;
                unpack2(p0[j], l0, h0); unpack2(p1[j], l1, h1);
                float ba = sm[OB2 + cb + 2*j], bbb = sm[OB2 + cb + 2*j + 1];
                sm[OH1 + (cb + 2*j)     * TEP + lane]      = silu_f(l0 + ba);
                sm[OH1 + (cb + 2*j + 1) * TEP + lane]      = silu_f(h0 + bbb);
                sm[OH1 + (cb + 2*j)     * TEP + lane + 32] = silu_f(l1 + ba);
                sm[OH1 + (cb + 2*j + 1) * TEP + lane + 32] = silu_f(h1 + bbb);
            }
        }
        __syncthreads();

        // ---- GEMM3: m = h2 @ W3 + b3 ; ms scatter + gv/gr ----
        {
            u64 p0[8], p1[8];
            #pragma unroll
            for (int j = 0; j < 8; ++j) { p0[j] = 0ull; p1[j] = 0ull; }
            const int cb3 = 16 * w;
            #pragma unroll 2
            for (int k = 0; k < HIDv; ++k) {
                u64 A0 = splat2(sm[OH1 + k * TEP + lane]);
                u64 A1 = splat2(sm[OH1 + k * TEP + lane + 32]);
                const ulonglong2* wr = (const ulonglong2*)&sm[OW3 + k * M3P + cb3];
                ulonglong2 w0 = wr[0], w1 = wr[1], w2 = wr[2], w3 = wr[3];
                ffma2(p0[0], A0, w0.x); ffma2(p0[1], A0, w0.y);
                ffma2(p0[2], A0, w1.x); ffma2(p0[3], A0, w1.y);
                ffma2(p0[4], A0, w2.x); ffma2(p0[5], A0, w2.y);
                ffma2(p0[6], A0, w3.x); ffma2(p0[7], A0, w3.y);
                ffma2(p1[0], A1, w0.x); ffma2(p1[1], A1, w0.y);
                ffma2(p1[2], A1, w1.x); ffma2(p1[3], A1, w1.y);
                ffma2(p1[4], A1, w2.x); ffma2(p1[5], A1, w2.y);
                ffma2(p1[6], A1, w3.x); ffma2(p1[7], A1, w3.y);
            }

            if (w < 6) {
                float g0 = 0.0f, g1 = 0.0f;
                #pragma unroll 4
                for (int k = 0; k < HIDv; ++k) {
                    float ww = sm[OW3 + k * M3P + 128 + w];
                    g0 += sm[OH1 + k * TEP + lane] * ww;
                    g1 += sm[OH1 + k * TEP + lane + 32] * ww;
                }
                float bb = sm[OB3 + 128 + w];
                gvg[w * 64 + lane]      = g0 + bb;
                gvg[w * 64 + lane + 32] = g1 + bb;
            }

            float c0 = Cs[lane], c1 = Cs[lane + 32];
            int dd0 = dstS[lane], dd1 = dstS[lane + 32];
            float m0[16], m1[16];
            #pragma unroll
            for (int j = 0; j < 8; ++j) {
                unpack2(p0[j], m0[2*j], m0[2*j+1]);
                unpack2(p1[j], m1[2*j], m1[2*j+1]);
            }
            float bb[16];
            #pragma unroll
            for (int j = 0; j < 16; ++j) bb[j] = sm[OB3 + cb3 + j];
            if (lane < ne) {
                float* bp = &g_sagg[(size_t)dd0 * SDv + cb3];
                #pragma unroll
                for (int j = 0; j < 4; ++j)
                    red4(bp + 4*j, (m0[4*j]+bb[4*j])*c0, (m0[4*j+1]+bb[4*j+1])*c0,
                                   (m0[4*j+2]+bb[4*j+2])*c0, (m0[4*j+3]+bb[4*j+3])*c0);
            }
            if (lane + 32 < ne) {
                float* bp = &g_sagg[(size_t)dd1 * SDv + cb3];
                #pragma unroll
                for (int j = 0; j < 4; ++j)
                    red4(bp + 4*j, (m1[4*j]+bb[4*j])*c1, (m1[4*j+1]+bb[4*j+1])*c1,
                                   (m1[4*j+2]+bb[4*j+2])*c1, (m1[4*j+3]+bb[4*j+3])*c1);
            }
        }
        __syncthreads();

        // vm scatter
        for (int idx = tid; idx < 9 * TILE; idx += NT) {
            int e = idx / 9;
            if (e >= ne) break;
            int c = idx - e * 9;
            int i3 = c / 3, j3 = c - i3 * 3;
            int se = srcS[e], de = dstS[e];
            float val = (g_v[(size_t)se * 9 + c] * gvg[i3 * 64 + e]
                       + rv[(size_t)(e0 + e) * 3 + j3] * gvg[(3 + i3) * 64 + e]) * Cs[e];
            atomicAdd(&g_vagg[(size_t)de * 9 + c], val);
        }
        __syncthreads();
    }
}

// -------------------- fused node kernel (2 CTAs/SM, 32-node tiles) --------------------
__global__ void __launch_bounds__(NT, 2)
k_node(const float* __restrict__ Wn1g, const float* __restrict__ bn1g,
       const float* __restrict__ Wn2g, const float* __restrict__ bn2g,
       int l)
{
    extern __shared__ float sm[];
    const int tid = threadIdx.x;
    const int w = tid >> 5, lane = tid & 31;

    const float* Wn1 = Wn1g + (size_t)l * 2 * SDv * HIDv;
    const float* bn1 = bn1g + l * HIDv;
    const float* Wn2 = Wn2g + (size_t)l * HIDv * SDv;   // stays in global (L1/L2)
    const float* bn2 = bn2g + l * SDv;

    for (int i = tid; i < 2 * SDv * HIDv; i += NT) sm[OWn1 + i] = Wn1[i];
    for (int i = tid; i < HIDv; i += NT) sm[OBn1 + i] = bn1[i];
    __syncthreads();

    for (int tile = blockIdx.x; tile < NTILES_N2; tile += gridDim.x) {
        const int n0 = tile * NTILE;
        const int nn = min(NTILE, Nn - n0);

        u64 pa[4];
        #pragma unroll
        for (int j = 0; j < 4; ++j) pa[j] = 0ull;
        const int cb = 8 * w;   // GEMM A cols for this warp

        // ---- pass 1: X = s[tile], accumulate over k=0..127 ----
        for (int i = tid; i < NTILE * SDv; i += NT) {
            int n = i >> 7, k = i & 127;
            sm[OX2 + k * NTP + n] = (n < nn) ? g_s[(size_t)(n0 + n) * SDv + k] : 0.0f;
        }
        __syncthreads();
        #pragma unroll 4
        for (int k = 0; k < SDv; ++k) {
            u64 A0 = splat2(sm[OX2 + k * NTP + lane]);
            const ulonglong2* wr = (const ulonglong2*)&sm[OWn1 + k * HIDv + cb];
            ulonglong2 w0 = wr[0], w1 = wr[1];
            ffma2(pa[0], A0, w0.x); ffma2(pa[1], A0, w0.y);
            ffma2(pa[2], A0, w1.x); ffma2(pa[3], A0, w1.y);
        }
        __syncthreads();

        // ---- pass 2: X = s_agg[tile], accumulate over k=128..255 ----
        for (int i = tid; i < NTILE * SDv; i += NT) {
            int n = i >> 7, k = i & 127;
            sm[OX2 + k * NTP + n] = (n < nn) ? g_sagg[(size_t)(n0 + n) * SDv + k] : 0.0f;
        }
        __syncthreads();
        #pragma unroll 4
        for (int k = 0; k < SDv; ++k) {
            u64 A0 = splat2(sm[OX2 + k * NTP + lane]);
            const ulonglong2* wr = (const ulonglong2*)&sm[OWn1 + (128 + k) * HIDv + cb];
            ulonglong2 w0 = wr[0], w1 = wr[1];
            ffma2(pa[0], A0, w0.x); ffma2(pa[1], A0, w0.y);
            ffma2(pa[2], A0, w1.x); ffma2(pa[3], A0, w1.y);
        }

        // write u = silu(acc + bn1) into U (k-major [h][n])
        #pragma unroll
        for (int j = 0; j < 4; ++j) {
            float lo, hi;
            unpack2(pa[j], lo, hi);
            float ba = sm[OBn1 + cb + 2*j], bbb = sm[OBn1 + cb + 2*j + 1];
            sm[OU2 + (cb + 2*j)     * NTP + lane] = silu_f(lo + ba);
            sm[OU2 + (cb + 2*j + 1) * NTP + lane] = silu_f(hi + bbb);
        }
        __syncthreads();

        // ---- GEMM B: s += u @ Wn2 + bn2 (Wn2 from global) ----
        {
            u64 pb[8];
            #pragma unroll
            for (int j = 0; j < 8; ++j) pb[j] = 0ull;
            const int cb3 = 16 * w;
            #pragma unroll 4
            for (int k = 0; k < HIDv; ++k) {
                u64 A0 = splat2(sm[OU2 + k * NTP + lane]);
                const float4* wg = (const float4*)&Wn2[k * SDv + cb3];
                float4 f0 = wg[0], f1 = wg[1], f2 = wg[2], f3 = wg[3];
                const ulonglong2* wr0 = (const ulonglong2*)&f0;
                const ulonglong2* wr1 = (const ulonglong2*)&f2;
                ffma2(pb[0], A0, ((const u64*)&f0)[0]); ffma2(pb[1], A0, ((const u64*)&f0)[1]);
                ffma2(pb[2], A0, ((const u64*)&f1)[0]); ffma2(pb[3], A0, ((const u64*)&f1)[1]);
                ffma2(pb[4], A0, ((const u64*)&f2)[0]); ffma2(pb[5], A0, ((const u64*)&f2)[1]);
                ffma2(pb[6], A0, ((const u64*)&f3)[0]); ffma2(pb[7], A0, ((const u64*)&f3)[1]);
                (void)wr0; (void)wr1;
            }
            if (lane < nn) {
                float* srow = &g_s[(size_t)(n0 + lane) * SDv + cb3];
                #pragma unroll
                for (int j = 0; j < 8; ++j) {
                    float lo, hi;
                    unpack2(pb[j], lo, hi);
                    srow[2*j]   += lo + bn2[cb3 + 2*j];
                    srow[2*j+1] += hi + bn2[cb3 + 2*j + 1];
                }
            }
        }

        // v += v_agg * inv_cnt
        for (int idx = tid; idx < 9 * NTILE; idx += NT) {
            int nl = idx / 9;
            if (nl >= nn) break;
            int c = idx - nl * 9;
            int n = n0 + nl;
            g_v[(size_t)n * 9 + c] += g_vagg[(size_t)n * 9 + c] * g_inv[n];
        }
        __syncthreads();
    }
}

// -------------------- launch --------------------
extern "C" void kernel_launch(void* const* d_in, const int* in_sizes, int n_in,
                              void* d_out, int out_size)
{
    const float* s   = (const float*)d_in[0];
    const float* v   = (const float*)d_in[1];
    const int*   ei  = (const int*)d_in[2];
    const float* dv  = (const float*)d_in[3];
    const float* rv  = (const float*)d_in[4];
    const float* W1  = (const float*)d_in[5];
    const float* b1  = (const float*)d_in[6];
    const float* W2  = (const float*)d_in[7];
    const float* b2  = (const float*)d_in[8];
    const float* W3  = (const float*)d_in[9];
    const float* b3  = (const float*)d_in[10];
    const float* Wn1 = (const float*)d_in[11];
    const float* bn1 = (const float*)d_in[12];
    const float* Wn2 = (const float*)d_in[13];
    const float* bn2 = (const float*)d_in[14];
    const int* dst = ei;
    const int* src = ei + Ee;

    cudaFuncSetAttribute(k_edge, cudaFuncAttributeMaxDynamicSharedMemorySize, SME_BYTES);
    cudaFuncSetAttribute(k_pq,   cudaFuncAttributeMaxDynamicSharedMemorySize, SMP_BYTES);
    cudaFuncSetAttribute(k_node, cudaFuncAttributeMaxDynamicSharedMemorySize, SMN_BYTES);

    // order arranged so k_edge is launch #4 (ncu capture slot)
    k_init<<<(Nn * SDv + 255) / 256, 256>>>(s, v);
    k_pq<<<296, NT, SMP_BYTES>>>(W1, 0);
    k_count<<<(Ee + 255) / 256, 256>>>(dst);
    k_edge<<<444, NT, SME_BYTES>>>(dst, src, dv, rv, W1, b1, W2, b2, W3, b3, 0);
    k_inv<<<(Nn + 255) / 256, 256>>>();
    k_node<<<296, NT, SMN_BYTES>>>(Wn1, bn1, Wn2, bn2, 0);

    for (int l = 1; l < 4; ++l) {
        k_pq<<<296, NT, SMP_BYTES>>>(W1, l);
        k_edge<<<444, NT, SME_BYTES>>>(dst, src, dv, rv, W1, b1, W2, b2, W3, b3, l);
        k_node<<<296, NT, SMN_BYTES>>>(Wn1, bn1, Wn2, bn2, l);
    }

    k_out<<<(Nn * SDv + 255) / 256, 256>>>((float*)d_out);
}

// round 5
// speedup vs baseline: 1.1821x; 1.1821x over previous
#include <cuda_runtime.h>
#include <math.h>

#define Nn   50000
#define Ee   500000
#define SDv  128
#define HIDv 64
#define K1v  257
#define M3v  134
#define M3P  136
#define TILE 64
#define TEP  65
#define TRS  68            // transpose buffer row stride (floats)
#define NT   256
#define NTILES_E ((Ee + TILE - 1) / TILE)
#define NTILES_N ((Nn + TILE - 1) / TILE)

// ---- edge-kernel shared memory (float offsets); H1 also used as transpose buf ----
#define OW2 0
#define OB2 (OW2 + HIDv*HIDv)          // 4096
#define OW3 (OB2 + HIDv)               // 4160
#define OB3 (OW3 + HIDv*M3P)           // 12864
#define OWD (OB3 + M3P)                // 13000
#define OB1 (OWD + HIDv)               // 13064
#define OH1 (OB1 + HIDv)               // 13128 ; region = max(64*65, 64*68)=4352
#define OMD (OH1 + TILE*TRS)           // 17480
#define OMS (OMD + TILE)
#define OMC (OMS + TILE)
#define ODD (OMC + TILE)
#define OGV (ODD + TILE)
#define SME_FLOATS (OGV + 6*TILE)      // 18120
#define SME_BYTES (SME_FLOATS * 4)     // 72480 B -> 3 CTAs/SM

// ---- PQ precompute kernel smem ----
#define OWpq 0
#define OXpq (OWpq + 128*128)
#define SMP_FLOATS (OXpq + SDv*TEP)
#define SMP_BYTES (SMP_FLOATS * 4)     // ~99 KB -> 2 CTAs/SM

// ---- node-kernel shared memory layout (R3 design) ----
#define OWn1 0
#define OBn1 (OWn1 + 2*SDv*HIDv)       // 16384
#define OWn2 (OBn1 + HIDv)             // 16448
#define OBn2 (OWn2 + HIDv*SDv)         // 24640
#define OX   (OBn2 + SDv)              // 24768
#define OU   (OX + 2*SDv*TEP)          // 41408
#define SMN_FLOATS (OU + HIDv*TEP)     // 45568
#define SMN_BYTES (SMN_FLOATS * 4)     // 182272 -> 1 CTA/SM

__device__ float g_s[(size_t)Nn * SDv];
__device__ float g_v[(size_t)Nn * 9];
__device__ float g_sagg[(size_t)Nn * SDv];
__device__ float g_vagg[(size_t)Nn * 9];
__device__ float g_pq[(size_t)Nn * 128];
__device__ float g_cnt[Nn];
__device__ float g_inv[Nn];

typedef unsigned long long u64;

__device__ __forceinline__ float silu_f(float x) { return x / (1.0f + __expf(-x)); }

__device__ __forceinline__ void red4(float* p, float a, float b, float c, float d) {
    asm volatile("red.global.add.v4.f32 [%0], {%1,%2,%3,%4};"
                 :: "l"(p), "f"(a), "f"(b), "f"(c), "f"(d) : "memory");
}
__device__ __forceinline__ u64 splat2(float a) {
    u64 r; asm("mov.b64 %0, {%1, %1};" : "=l"(r) : "f"(a)); return r;
}
__device__ __forceinline__ void ffma2(u64& acc, u64 a2, u64 w2) {
    asm("fma.rn.f32x2 %0, %1, %2, %0;" : "+l"(acc) : "l"(a2), "l"(w2));
}
__device__ __forceinline__ void unpack2(u64 p, float& lo, float& hi) {
    asm("mov.b64 {%0, %1}, %2;" : "=f"(lo), "=f"(hi) : "l"(p));
}

// -------------------- init / misc --------------------
__global__ void k_init(const float* __restrict__ s, const float* __restrict__ v) {
    int i = blockIdx.x * blockDim.x + threadIdx.x;
    if (i < Nn * SDv) g_s[i] = s[i];
    if (i < Nn * 9)   g_v[i] = v[i];
    if (i < Nn)       g_cnt[i] = 0.0f;
}
__global__ void k_count(const int* __restrict__ dst) {
    int e = blockIdx.x * blockDim.x + threadIdx.x;
    if (e < Ee) atomicAdd(&g_cnt[dst[e]], 1.0f);
}
__global__ void k_inv() {
    int i = blockIdx.x * blockDim.x + threadIdx.x;
    if (i < Nn) g_inv[i] = 1.0f / fmaxf(g_cnt[i], 1.0f);
}
__global__ void k_out(float* __restrict__ out) {
    int i = blockIdx.x * blockDim.x + threadIdx.x;
    if (i < Nn * SDv) out[i] = g_s[i];
    if (i < Nn * 9)   out[(size_t)Nn * SDv + i] = g_v[i];
}

// -------------------- PQ precompute (+ zero agg) --------------------
__global__ void __launch_bounds__(NT, 2)
k_pq(const float* __restrict__ W1g, int l)
{
    extern __shared__ float sm[];
    const int tid = threadIdx.x;
    const int w = tid >> 5, lane = tid & 31;
    const float* W1 = W1g + (size_t)l * K1v * HIDv;

    for (int i = blockIdx.x * NT + tid; i < Nn * SDv; i += gridDim.x * NT) g_sagg[i] = 0.0f;
    for (int i = blockIdx.x * NT + tid; i < Nn * 9; i += gridDim.x * NT) g_vagg[i] = 0.0f;

    for (int i = tid; i < 128 * 128; i += NT) {
        int k = i >> 7, c = i & 127;
        sm[OWpq + i] = (c < 64) ? W1[k * 64 + c] : W1[(128 + k) * 64 + (c - 64)];
    }
    __syncthreads();

    for (int tile = blockIdx.x; tile < NTILES_N; tile += gridDim.x) {
        const int n0 = tile * TILE;
        const int nn = min(TILE, Nn - n0);

        for (int i = tid; i < TILE * SDv; i += NT) {
            int n = i >> 7, k = i & 127;
            sm[OXpq + k * TEP + n] = (n < nn) ? g_s[(size_t)(n0 + n) * SDv + k] : 0.0f;
        }
        __syncthreads();

        {
            u64 p0[8], p1[8];
            #pragma unroll
            for (int j = 0; j < 8; ++j) { p0[j] = 0ull; p1[j] = 0ull; }
            const int cb = 16 * w;
            #pragma unroll 2
            for (int k = 0; k < 128; ++k) {
                u64 A0 = splat2(sm[OXpq + k * TEP + lane]);
                u64 A1 = splat2(sm[OXpq + k * TEP + lane + 32]);
                const ulonglong2* wr = (const ulonglong2*)&sm[OWpq + k * 128 + cb];
                ulonglong2 w0 = wr[0], w1 = wr[1], w2 = wr[2], w3 = wr[3];
                ffma2(p0[0], A0, w0.x); ffma2(p0[1], A0, w0.y);
                ffma2(p0[2], A0, w1.x); ffma2(p0[3], A0, w1.y);
                ffma2(p0[4], A0, w2.x); ffma2(p0[5], A0, w2.y);
                ffma2(p0[6], A0, w3.x); ffma2(p0[7], A0, w3.y);
                ffma2(p1[0], A1, w0.x); ffma2(p1[1], A1, w0.y);
                ffma2(p1[2], A1, w1.x); ffma2(p1[3], A1, w1.y);
                ffma2(p1[4], A1, w2.x); ffma2(p1[5], A1, w2.y);
                ffma2(p1[6], A1, w3.x); ffma2(p1[7], A1, w3.y);
            }
            if (lane < nn) {
                float* op = &g_pq[(size_t)(n0 + lane) * 128 + cb];
                #pragma unroll
                for (int j = 0; j < 8; ++j) { float lo, hi; unpack2(p0[j], lo, hi); op[2*j] = lo; op[2*j+1] = hi; }
            }
            if (lane + 32 < nn) {
                float* op = &g_pq[(size_t)(n0 + lane + 32) * 128 + cb];
                #pragma unroll
                for (int j = 0; j < 8; ++j) { float lo, hi; unpack2(p1[j], lo, hi); op[2*j] = lo; op[2*j+1] = hi; }
            }
        }
        __syncthreads();
    }
}

// -------------------- fused edge kernel (3 CTAs/SM, coalesced scatter) --------------------
__global__ void __launch_bounds__(NT, 3)
k_edge(const int* __restrict__ dst, const int* __restrict__ src,
       const float* __restrict__ dv, const float* __restrict__ rv,
       const float* __restrict__ W1g, const float* __restrict__ b1g,
       const float* __restrict__ W2g, const float* __restrict__ b2g,
       const float* __restrict__ W3g, const float* __restrict__ b3g,
       int l)
{
    extern __shared__ float sm[];
    const int tid = threadIdx.x;
    const int w = tid >> 5, lane = tid & 31;

    const float* W1 = W1g + (size_t)l * K1v * HIDv;
    const float* b1 = b1g + l * HIDv;
    const float* W2 = W2g + l * HIDv * HIDv;
    const float* b2 = b2g + l * HIDv;
    const float* W3 = W3g + l * HIDv * M3v;
    const float* b3 = b3g + l * M3v;

    for (int i = tid; i < HIDv * HIDv; i += NT) sm[OW2 + i] = W2[i];
    for (int i = tid; i < HIDv * M3v; i += NT) {
        int k = i / M3v, c = i - k * M3v;
        sm[OW3 + k * M3P + c] = W3[i];
    }
    for (int i = tid; i < M3v; i += NT) sm[OB3 + i] = b3[i];
    for (int i = tid; i < HIDv; i += NT) {
        sm[OB2 + i] = b2[i];
        sm[OB1 + i] = b1[i];
        sm[OWD + i] = W1[256 * 64 + i];
    }
    __syncthreads();

    int*   dstS = (int*)&sm[OMD];
    int*   srcS = (int*)&sm[OMS];
    float* Cs   = &sm[OMC];
    float* dds  = &sm[ODD];
    float* gvg  = &sm[OGV];

    for (int tile = blockIdx.x; tile < NTILES_E; tile += gridDim.x) {
        const int e0 = tile * TILE;
        const int ne = min(TILE, Ee - e0);

        if (tid < TILE) {
            if (tid < ne) {
                dstS[tid] = dst[e0 + tid];
                srcS[tid] = src[e0 + tid];
                float dd = dv[e0 + tid];
                dds[tid] = dd;
                Cs[tid] = (dd < 5.0f) ? 0.5f * (cosf(0.62831853071795864769f * dd) + 1.0f) : 0.0f;
            } else {
                dstS[tid] = 0; srcS[tid] = 0; Cs[tid] = 0.0f; dds[tid] = 0.0f;
            }
        }
        __syncthreads();

        // h1[e] = silu(P[dst] + Q[src] + d*wd + b1)  -> k-major smem (stride TEP)
        {
            const int ebase = w * 8;
            float wd0 = sm[OWD + lane], wd1 = sm[OWD + lane + 32];
            float bb0 = sm[OB1 + lane], bb1 = sm[OB1 + lane + 32];
            for (int q = 0; q < 8; ++q) {
                int ee = ebase + q;
                if (ee < ne) {
                    const float* pp = &g_pq[(size_t)dstS[ee] * 128];
                    const float* qq = &g_pq[(size_t)srcS[ee] * 128 + 64];
                    float de = dds[ee];
                    float h0  = pp[lane]      + qq[lane]      + de * wd0 + bb0;
                    float h1v = pp[lane + 32] + qq[lane + 32] + de * wd1 + bb1;
                    sm[OH1 + lane * TEP + ee]        = silu_f(h0);
                    sm[OH1 + (lane + 32) * TEP + ee] = silu_f(h1v);
                } else {
                    sm[OH1 + lane * TEP + ee]        = 0.0f;
                    sm[OH1 + (lane + 32) * TEP + ee] = 0.0f;
                }
            }
        }
        __syncthreads();

        // ---- GEMM2: h2 = silu(h1 @ W2 + b2); result overwrites H1 ----
        {
            u64 p0[4], p1[4];
            #pragma unroll
            for (int j = 0; j < 4; ++j) { p0[j] = 0ull; p1[j] = 0ull; }
            const int cb = 8 * w;
            #pragma unroll 4
            for (int k = 0; k < HIDv; ++k) {
                u64 A0 = splat2(sm[OH1 + k * TEP + lane]);
                u64 A1 = splat2(sm[OH1 + k * TEP + lane + 32]);
                const ulonglong2* wr = (const ulonglong2*)&sm[OW2 + k * HIDv + cb];
                ulonglong2 w0 = wr[0], w1 = wr[1];
                ffma2(p0[0], A0, w0.x); ffma2(p0[1], A0, w0.y);
                ffma2(p0[2], A0, w1.x); ffma2(p0[3], A0, w1.y);
                ffma2(p1[0], A1, w0.x); ffma2(p1[1], A1, w0.y);
                ffma2(p1[2], A1, w1.x); ffma2(p1[3], A1, w1.y);
            }
            __syncthreads();
            #pragma unroll
            for (int j = 0; j < 4; ++j) {
                float l0, h0, l1, h1;
                unpack2(p0[j], l0, h0); unpack2(p1[j], l1, h1);
                float ba = sm[OB2 + cb + 2*j], bbb = sm[OB2 + cb + 2*j + 1];
                sm[OH1 + (cb + 2*j)     * TEP + lane]      = silu_f(l0 + ba);
                sm[OH1 + (cb + 2*j + 1) * TEP + lane]      = silu_f(h0 + bbb);
                sm[OH1 + (cb + 2*j)     * TEP + lane + 32] = silu_f(l1 + ba);
                sm[OH1 + (cb + 2*j + 1) * TEP + lane + 32] = silu_f(h1 + bbb);
            }
        }
        __syncthreads();

        // ---- GEMM3 + gv/gr, then coalesced scatter via smem transpose ----
        {
            u64 p0[8], p1[8];
            #pragma unroll
            for (int j = 0; j < 8; ++j) { p0[j] = 0ull; p1[j] = 0ull; }
            const int cb3 = 16 * w;
            #pragma unroll 2
            for (int k = 0; k < HIDv; ++k) {
                u64 A0 = splat2(sm[OH1 + k * TEP + lane]);
                u64 A1 = splat2(sm[OH1 + k * TEP + lane + 32]);
                const ulonglong2* wr = (const ulonglong2*)&sm[OW3 + k * M3P + cb3];
                ulonglong2 w0 = wr[0], w1 = wr[1], w2 = wr[2], w3 = wr[3];
                ffma2(p0[0], A0, w0.x); ffma2(p0[1], A0, w0.y);
                ffma2(p0[2], A0, w1.x); ffma2(p0[3], A0, w1.y);
                ffma2(p0[4], A0, w2.x); ffma2(p0[5], A0, w2.y);
                ffma2(p0[6], A0, w3.x); ffma2(p0[7], A0, w3.y);
                ffma2(p1[0], A1, w0.x); ffma2(p1[1], A1, w0.y);
                ffma2(p1[2], A1, w1.x); ffma2(p1[3], A1, w1.y);
                ffma2(p1[4], A1, w2.x); ffma2(p1[5], A1, w2.y);
                ffma2(p1[6], A1, w3.x); ffma2(p1[7], A1, w3.y);
            }

            if (w < 6) {
                float g0 = 0.0f, g1 = 0.0f;
                #pragma unroll 4
                for (int k = 0; k < HIDv; ++k) {
                    float ww = sm[OW3 + k * M3P + 128 + w];
                    g0 += sm[OH1 + k * TEP + lane] * ww;
                    g1 += sm[OH1 + k * TEP + lane + 32] * ww;
                }
                float bb = sm[OB3 + 128 + w];
                gvg[w * 64 + lane]      = g0 + bb;
                gvg[w * 64 + lane + 32] = g1 + bb;
            }

            // finalize m = (acc + b3) * C in registers
            float c0 = Cs[lane], c1 = Cs[lane + 32];
            float m0[16], m1[16];
            #pragma unroll
            for (int j = 0; j < 8; ++j) {
                unpack2(p0[j], m0[2*j], m0[2*j+1]);
                unpack2(p1[j], m1[2*j], m1[2*j+1]);
            }
            #pragma unroll
            for (int j = 0; j < 16; ++j) {
                float bb = sm[OB3 + cb3 + j];
                m0[j] = (m0[j] + bb) * c0;
                m1[j] = (m1[j] + bb) * c1;
            }
            __syncthreads();   // all H1/gvg reads done; H1 reusable as transpose buf

            const int half0 = (w < 4) ? 0 : 1;
            const int cbh = cb3 - half0 * 64;  // column offset within half

            // ---- pass over both halves: 0 then 1 ----
            #pragma unroll
            for (int half = 0; half < 2; ++half) {
                if (half0 == half) {
                    // write m tiles: addr = e*TRS + cbh (+j), conflict-free STS.128
                    float4* t0 = (float4*)&sm[OH1 + lane * TRS + cbh];
                    float4* t1 = (float4*)&sm[OH1 + (lane + 32) * TRS + cbh];
                    t0[0] = make_float4(m0[0], m0[1], m0[2], m0[3]);
                    t0[1] = make_float4(m0[4], m0[5], m0[6], m0[7]);
                    t0[2] = make_float4(m0[8], m0[9], m0[10], m0[11]);
                    t0[3] = make_float4(m0[12], m0[13], m0[14], m0[15]);
                    t1[0] = make_float4(m1[0], m1[1], m1[2], m1[3]);
                    t1[1] = make_float4(m1[4], m1[5], m1[6], m1[7]);
                    t1[2] = make_float4(m1[8], m1[9], m1[10], m1[11]);
                    t1[3] = make_float4(m1[12], m1[13], m1[14], m1[15]);
                }
                __syncthreads();
                // coalesced scatter: lanes 0-15 -> edge ea, lanes 16-31 -> edge eb
                #pragma unroll
                for (int it = 0; it < 4; ++it) {
                    int e = w * 8 + it * 2 + (lane >> 4);
                    int c4 = (lane & 15) * 4;
                    float4 val = *(const float4*)&sm[OH1 + e * TRS + c4];
                    float* bp = &g_sagg[(size_t)dstS[e] * SDv + half * 64 + c4];
                    red4(bp, val.x, val.y, val.z, val.w);
                }
                __syncthreads();
            }
        }

        // vm scatter (gvg valid; Cs/srcS unchanged)
        for (int idx = tid; idx < 9 * TILE; idx += NT) {
            int e = idx / 9;
            if (e >= ne) break;
            int c = idx - e * 9;
            int i3 = c / 3, j3 = c - i3 * 3;
            int se = srcS[e], de = dstS[e];
            float val = (g_v[(size_t)se * 9 + c] * gvg[i3 * 64 + e]
                       + rv[(size_t)(e0 + e) * 3 + j3] * gvg[(3 + i3) * 64 + e]) * Cs[e];
            atomicAdd(&g_vagg[(size_t)de * 9 + c], val);
        }
        __syncthreads();
    }
}

// -------------------- fused node kernel (R3 design) --------------------
__global__ void __launch_bounds__(NT, 1)
k_node(const float* __restrict__ Wn1g, const float* __restrict__ bn1g,
       const float* __restrict__ Wn2g, const float* __restrict__ bn2g,
       int l)
{
    extern __shared__ float sm[];
    const int tid = threadIdx.x;
    const int w = tid >> 5, lane = tid & 31;

    const float* Wn1 = Wn1g + (size_t)l * 2 * SDv * HIDv;
    const float* bn1 = bn1g + l * HIDv;
    const float* Wn2 = Wn2g + (size_t)l * HIDv * SDv;
    const float* bn2 = bn2g + l * SDv;

    for (int i = tid; i < 2 * SDv * HIDv; i += NT) sm[OWn1 + i] = Wn1[i];
    for (int i = tid; i < HIDv; i += NT) sm[OBn1 + i] = bn1[i];
    for (int i = tid; i < HIDv * SDv; i += NT) sm[OWn2 + i] = Wn2[i];
    for (int i = tid; i < SDv; i += NT) sm[OBn2 + i] = bn2[i];
    __syncthreads();

    for (int tile = blockIdx.x; tile < NTILES_N; tile += gridDim.x) {
        const int n0 = tile * TILE;
        const int nn = min(TILE, Nn - n0);

        for (int i = tid; i < TILE * SDv; i += NT) {
            int n = i >> 7, k = i & 127;
            float a = 0.0f, b = 0.0f;
            if (n < nn) {
                a = g_s[(size_t)(n0 + n) * SDv + k];
                b = g_sagg[(size_t)(n0 + n) * SDv + k];
            }
            sm[OX + k * TEP + n]         = a;
            sm[OX + (128 + k) * TEP + n] = b;
        }
        __syncthreads();

        // GEMM A: u = silu(x @ Wn1 + bn1), K=256, f32x2
        {
            u64 p0[4], p1[4];
            #pragma unroll
            for (int j = 0; j < 4; ++j) { p0[j] = 0ull; p1[j] = 0ull; }
            const int cb = 8 * w;
            #pragma unroll 4
            for (int k = 0; k < 2 * SDv; ++k) {
                u64 A0 = splat2(sm[OX + k * TEP + lane]);
                u64 A1 = splat2(sm[OX + k * TEP + lane + 32]);
                const ulonglong2* wr = (const ulonglong2*)&sm[OWn1 + k * HIDv + cb];
                ulonglong2 w0 = wr[0], w1 = wr[1];
                ffma2(p0[0], A0, w0.x); ffma2(p0[1], A0, w0.y);
                ffma2(p0[2], A0, w1.x); ffma2(p0[3], A0, w1.y);
                ffma2(p1[0], A1, w0.x); ffma2(p1[1], A1, w0.y);
                ffma2(p1[2], A1, w1.x); ffma2(p1[3], A1, w1.y);
            }
            #pragma unroll
            for (int j = 0; j < 4; ++j) {
                float l0, h0, l1, h1;
                unpack2(p0[j], l0, h0); unpack2(p1[j], l1, h1);
                float ba = sm[OBn1 + cb + 2*j], bbb = sm[OBn1 + cb + 2*j + 1];
                sm[OU + (cb + 2*j)     * TEP + lane]      = silu_f(l0 + ba);
                sm[OU + (cb + 2*j + 1) * TEP + lane]      = silu_f(h0 + bbb);
                sm[OU + (cb + 2*j)     * TEP + lane + 32] = silu_f(l1 + ba);
                sm[OU + (cb + 2*j + 1) * TEP + lane + 32] = silu_f(h1 + bbb);
            }
        }
        __syncthreads();

        // GEMM B: s += u @ Wn2 + bn2, f32x2
        {
            u64 p0[8], p1[8];
            #pragma unroll
            for (int j = 0; j < 8; ++j) { p0[j] = 0ull; p1[j] = 0ull; }
            const int cb3 = 16 * w;
            #pragma unroll 2
            for (int k = 0; k < HIDv; ++k) {
                u64 A0 = splat2(sm[OU + k * TEP + lane]);
                u64 A1 = splat2(sm[OU + k * TEP + lane + 32]);
                const ulonglong2* wr = (const ulonglong2*)&sm[OWn2 + k * SDv + cb3];
                ulonglong2 w0 = wr[0], w1 = wr[1], w2 = wr[2], w3 = wr[3];
                ffma2(p0[0], A0, w0.x); ffma2(p0[1], A0, w0.y);
                ffma2(p0[2], A0, w1.x); ffma2(p0[3], A0, w1.y);
                ffma2(p0[4], A0, w2.x); ffma2(p0[5], A0, w2.y);
                ffma2(p0[6], A0, w3.x); ffma2(p0[7], A0, w3.y);
                ffma2(p1[0], A1, w0.x); ffma2(p1[1], A1, w0.y);
                ffma2(p1[2], A1, w1.x); ffma2(p1[3], A1, w1.y);
                ffma2(p1[4], A1, w2.x); ffma2(p1[5], A1, w2.y);
                ffma2(p1[6], A1, w3.x); ffma2(p1[7], A1, w3.y);
            }
            float m0[16], m1[16];
            #pragma unroll
            for (int j = 0; j < 8; ++j) {
                unpack2(p0[j], m0[2*j], m0[2*j+1]);
                unpack2(p1[j], m1[2*j], m1[2*j+1]);
            }
            #pragma unroll
            for (int j = 0; j < 16; ++j) {
                int c = cb3 + j;
                float bb = sm[OBn2 + c];
                if (lane < nn) {
                    float old = sm[OX + c * TEP + lane];
                    g_s[(size_t)(n0 + lane) * SDv + c] = old + m0[j] + bb;
                }
                if (lane + 32 < nn) {
                    float old = sm[OX + c * TEP + lane + 32];
                    g_s[(size_t)(n0 + lane + 32) * SDv + c] = old + m1[j] + bb;
                }
            }
        }

        // v += v_agg * inv_cnt
        for (int idx = tid; idx < 9 * TILE; idx += NT) {
            int nl = idx / 9;
            if (nl >= nn) break;
            int c = idx - nl * 9;
            int n = n0 + nl;
            g_v[(size_t)n * 9 + c] += g_vagg[(size_t)n * 9 + c] * g_inv[n];
        }
        __syncthreads();
    }
}

// -------------------- launch --------------------
extern "C" void kernel_launch(void* const* d_in, const int* in_sizes, int n_in,
                              void* d_out, int out_size)
{
    const float* s   = (const float*)d_in[0];
    const float* v   = (const float*)d_in[1];
    const int*   ei  = (const int*)d_in[2];
    const float* dv  = (const float*)d_in[3];
    const float* rv  = (const float*)d_in[4];
    const float* W1  = (const float*)d_in[5];
    const float* b1  = (const float*)d_in[6];
    const float* W2  = (const float*)d_in[7];
    const float* b2  = (const float*)d_in[8];
    const float* W3  = (const float*)d_in[9];
    const float* b3  = (const float*)d_in[10];
    const float* Wn1 = (const float*)d_in[11];
    const float* bn1 = (const float*)d_in[12];
    const float* Wn2 = (const float*)d_in[13];
    const float* bn2 = (const float*)d_in[14];
    const int* dst = ei;
    const int* src = ei + Ee;

    cudaFuncSetAttribute(k_edge, cudaFuncAttributeMaxDynamicSharedMemorySize, SME_BYTES);
    cudaFuncSetAttribute(k_pq,   cudaFuncAttributeMaxDynamicSharedMemorySize, SMP_BYTES);
    cudaFuncSetAttribute(k_node, cudaFuncAttributeMaxDynamicSharedMemorySize, SMN_BYTES);

    // order arranged so k_edge is launch #4 (ncu capture slot)
    k_init<<<(Nn * SDv + 255) / 256, 256>>>(s, v);
    k_pq<<<296, NT, SMP_BYTES>>>(W1, 0);
    k_count<<<(Ee + 255) / 256, 256>>>(dst);
    k_edge<<<444, NT, SME_BYTES>>>(dst, src, dv, rv, W1, b1, W2, b2, W3, b3, 0);
    k_inv<<<(Nn + 255) / 256, 256>>>();
    k_node<<<148, NT, SMN_BYTES>>>(Wn1, bn1, Wn2, bn2, 0);

    for (int l = 1; l < 4; ++l) {
        k_pq<<<296, NT, SMP_BYTES>>>(W1, l);
        k_edge<<<444, NT, SME_BYTES>>>(dst, src, dv, rv, W1, b1, W2, b2, W3, b3, l);
        k_node<<<148, NT, SMN_BYTES>>>(Wn1, bn1, Wn2, bn2, l);
    }

    k_out<<<(Nn * SDv + 255) / 256, 256>>>((float*)d_out);
}

// round 6
// speedup vs baseline: 1.2424x; 1.0510x over previous
#include <cuda_runtime.h>
#include <math.h>

#define Nn   50000
#define Ee   500000
#define SDv  128
#define HIDv 64
#define K1v  257
#define M3v  134
#define M3P  136
#define TILE 64
#define TEP  65
#define TRS  68
#define NT   256
#define NTILES_E ((Ee + TILE - 1) / TILE)
#define NTILES_N ((Nn + TILE - 1) / TILE)

// ---- edge-kernel shared memory ----
#define OW2 0
#define OB2 (OW2 + HIDv*HIDv)
#define OW3 (OB2 + HIDv)
#define OB3 (OW3 + HIDv*M3P)
#define OWD (OB3 + M3P)
#define OB1 (OWD + HIDv)
#define OH1 (OB1 + HIDv)
#define OMD (OH1 + TILE*TRS)
#define OMS (OMD + TILE)
#define OMC (OMS + TILE)
#define ODD (OMC + TILE)
#define OGV (ODD + TILE)
#define SME_FLOATS (OGV + 6*TILE)
#define SME_BYTES (SME_FLOATS * 4)     // ~72.5 KB -> 3 CTAs/SM

// ---- PQ kernel smem ----
#define OWpq 0
#define OXpq (OWpq + 128*128)
#define SMP_FLOATS (OXpq + SDv*TEP)
#define SMP_BYTES (SMP_FLOATS * 4)     // ~99 KB -> 2 CTAs/SM

// ---- node kernel smem ----
#define OWn1 0
#define OBn1 (OWn1 + 2*SDv*HIDv)
#define OWn2 (OBn1 + HIDv)
#define OBn2 (OWn2 + HIDv*SDv)
#define OX   (OBn2 + SDv)
#define OU   (OX + 2*SDv*TEP)
#define SMN_FLOATS (OU + HIDv*TEP)
#define SMN_BYTES (SMN_FLOATS * 4)

__device__ float g_s[(size_t)Nn * SDv];
__device__ float g_v[(size_t)Nn * 9];
__device__ float g_sagg[(size_t)Nn * SDv];
__device__ float g_vagg[(size_t)Nn * 9];
__device__ float g_pq[(size_t)Nn * 128];
__device__ float g_cnt[Nn];
__device__ float g_inv[Nn];

typedef unsigned long long u64;

__device__ __forceinline__ float silu_f(float x) { return x / (1.0f + __expf(-x)); }

__device__ __forceinline__ void red4(float* p, float a, float b, float c, float d) {
    asm volatile("red.global.add.v4.f32 [%0], {%1,%2,%3,%4};"
                 :: "l"(p), "f"(a), "f"(b), "f"(c), "f"(d) : "memory");
}
__device__ __forceinline__ u64 splat2(float a) {
    u64 r; asm("mov.b64 %0, {%1, %1};" : "=l"(r) : "f"(a)); return r;
}
__device__ __forceinline__ void ffma2(u64& acc, u64 a2, u64 w2) {
    asm("fma.rn.f32x2 %0, %1, %2, %0;" : "+l"(acc) : "l"(a2), "l"(w2));
}
__device__ __forceinline__ void unpack2(u64 p, float& lo, float& hi) {
    asm("mov.b64 {%0, %1}, %2;" : "=f"(lo), "=f"(hi) : "l"(p));
}

// -------------------- init / misc --------------------
__global__ void k_init(const float* __restrict__ s, const float* __restrict__ v) {
    int i = blockIdx.x * blockDim.x + threadIdx.x;
    if (i < Nn * SDv) g_s[i] = s[i];
    if (i < Nn * 9)   g_v[i] = v[i];
    if (i < Nn)       g_cnt[i] = 0.0f;
}
__global__ void k_count(const int* __restrict__ dst) {
    int e = blockIdx.x * blockDim.x + threadIdx.x;
    if (e < Ee) atomicAdd(&g_cnt[dst[e]], 1.0f);
}
__global__ void k_inv() {
    int i = blockIdx.x * blockDim.x + threadIdx.x;
    if (i < Nn) g_inv[i] = 1.0f / fmaxf(g_cnt[i], 1.0f);
}

// -------------------- PQ precompute (+ zero agg) --------------------
__global__ void __launch_bounds__(NT, 2)
k_pq(const float* __restrict__ W1g, int l)
{
    extern __shared__ float sm[];
    const int tid = threadIdx.x;
    const int w = tid >> 5, lane = tid & 31;
    const float* W1 = W1g + (size_t)l * K1v * HIDv;

    for (int i = blockIdx.x * NT + tid; i < Nn * SDv; i += gridDim.x * NT) g_sagg[i] = 0.0f;
    for (int i = blockIdx.x * NT + tid; i < Nn * 9; i += gridDim.x * NT) g_vagg[i] = 0.0f;

    for (int i = tid; i < 128 * 128; i += NT) {
        int k = i >> 7, c = i & 127;
        sm[OWpq + i] = (c < 64) ? W1[k * 64 + c] : W1[(128 + k) * 64 + (c - 64)];
    }
    __syncthreads();

    for (int tile = blockIdx.x; tile < NTILES_N; tile += gridDim.x) {
        const int n0 = tile * TILE;
        const int nn = min(TILE, Nn - n0);

        #pragma unroll 4
        for (int i = tid; i < TILE * SDv; i += NT) {
            int n = i >> 7, k = i & 127;
            sm[OXpq + k * TEP + n] = (n < nn) ? g_s[(size_t)(n0 + n) * SDv + k] : 0.0f;
        }
        __syncthreads();

        {
            u64 p0[8], p1[8];
            #pragma unroll
            for (int j = 0; j < 8; ++j) { p0[j] = 0ull; p1[j] = 0ull; }
            const int cb = 16 * w;
            #pragma unroll 2
            for (int k = 0; k < 128; ++k) {
                u64 A0 = splat2(sm[OXpq + k * TEP + lane]);
                u64 A1 = splat2(sm[OXpq + k * TEP + lane + 32]);
                const ulonglong2* wr = (const ulonglong2*)&sm[OWpq + k * 128 + cb];
                ulonglong2 w0 = wr[0], w1 = wr[1], w2 = wr[2], w3 = wr[3];
                ffma2(p0[0], A0, w0.x); ffma2(p0[1], A0, w0.y);
                ffma2(p0[2], A0, w1.x); ffma2(p0[3], A0, w1.y);
                ffma2(p0[4], A0, w2.x); ffma2(p0[5], A0, w2.y);
                ffma2(p0[6], A0, w3.x); ffma2(p0[7], A0, w3.y);
                ffma2(p1[0], A1, w0.x); ffma2(p1[1], A1, w0.y);
                ffma2(p1[2], A1, w1.x); ffma2(p1[3], A1, w1.y);
                ffma2(p1[4], A1, w2.x); ffma2(p1[5], A1, w2.y);
                ffma2(p1[6], A1, w3.x); ffma2(p1[7], A1, w3.y);
            }
            if (lane < nn) {
                float* op = &g_pq[(size_t)(n0 + lane) * 128 + cb];
                #pragma unroll
                for (int j = 0; j < 8; ++j) { float lo, hi; unpack2(p0[j], lo, hi); op[2*j] = lo; op[2*j+1] = hi; }
            }
            if (lane + 32 < nn) {
                float* op = &g_pq[(size_t)(n0 + lane + 32) * 128 + cb];
                #pragma unroll
                for (int j = 0; j < 8; ++j) { float lo, hi; unpack2(p1[j], lo, hi); op[2*j] = lo; op[2*j+1] = hi; }
            }
        }
        __syncthreads();
    }
}

// -------------------- fused edge kernel --------------------
__global__ void __launch_bounds__(NT, 3)
k_edge(const int* __restrict__ dst, const int* __restrict__ src,
       const float* __restrict__ dv, const float* __restrict__ rv,
       const float* __restrict__ W1g, const float* __restrict__ b1g,
       const float* __restrict__ W2g, const float* __restrict__ b2g,
       const float* __restrict__ W3g, const float* __restrict__ b3g,
       int l)
{
    extern __shared__ float sm[];
    const int tid = threadIdx.x;
    const int w = tid >> 5, lane = tid & 31;

    const float* W1 = W1g + (size_t)l * K1v * HIDv;
    const float* b1 = b1g + l * HIDv;
    const float* W2 = W2g + l * HIDv * HIDv;
    const float* b2 = b2g + l * HIDv;
    const float* W3 = W3g + l * HIDv * M3v;
    const float* b3 = b3g + l * M3v;

    for (int i = tid; i < HIDv * HIDv; i += NT) sm[OW2 + i] = W2[i];
    for (int i = tid; i < HIDv * M3v; i += NT) {
        int k = i / M3v, c = i - k * M3v;
        sm[OW3 + k * M3P + c] = W3[i];
    }
    for (int i = tid; i < M3v; i += NT) sm[OB3 + i] = b3[i];
    for (int i = tid; i < HIDv; i += NT) {
        sm[OB2 + i] = b2[i];
        sm[OB1 + i] = b1[i];
        sm[OWD + i] = W1[256 * 64 + i];
    }
    __syncthreads();

    int*   dstS = (int*)&sm[OMD];
    int*   srcS = (int*)&sm[OMS];
    float* Cs   = &sm[OMC];
    float* dds  = &sm[ODD];
    float* gvg  = &sm[OGV];

    for (int tile = blockIdx.x; tile < NTILES_E; tile += gridDim.x) {
        const int e0 = tile * TILE;
        const int ne = min(TILE, Ee - e0);

        if (tid < TILE) {
            if (tid < ne) {
                dstS[tid] = dst[e0 + tid];
                srcS[tid] = src[e0 + tid];
                float dd = dv[e0 + tid];
                dds[tid] = dd;
                Cs[tid] = (dd < 5.0f) ? 0.5f * (cosf(0.62831853071795864769f * dd) + 1.0f) : 0.0f;
            } else {
                dstS[tid] = 0; srcS[tid] = 0; Cs[tid] = 0.0f; dds[tid] = 0.0f;
            }
        }
        __syncthreads();

        // h1[e] = silu(P[dst] + Q[src] + d*wd + b1), batched LDG for MLP
        {
            const int ebase = w * 8;
            float wd0 = sm[OWD + lane], wd1 = sm[OWD + lane + 32];
            float bb0 = sm[OB1 + lane], bb1 = sm[OB1 + lane + 32];
            #pragma unroll
            for (int qb = 0; qb < 2; ++qb) {
                const int e4 = ebase + qb * 4;
                float P0[4], P1[4], Q0[4], Q1[4];
                // issue all 16 loads before any use (padded edges read row 0, gated later by C=0)
                #pragma unroll
                for (int j = 0; j < 4; ++j) {
                    const float* pp = &g_pq[(size_t)dstS[e4 + j] * 128];
                    const float* qq = &g_pq[(size_t)srcS[e4 + j] * 128 + 64];
                    P0[j] = pp[lane]; P1[j] = pp[lane + 32];
                    Q0[j] = qq[lane]; Q1[j] = qq[lane + 32];
                }
                #pragma unroll
                for (int j = 0; j < 4; ++j) {
                    int ee = e4 + j;
                    float de = dds[ee];
                    float h0  = P0[j] + Q0[j] + de * wd0 + bb0;
                    float h1v = P1[j] + Q1[j] + de * wd1 + bb1;
                    sm[OH1 + lane * TEP + ee]        = silu_f(h0);
                    sm[OH1 + (lane + 32) * TEP + ee] = silu_f(h1v);
                }
            }
        }
        __syncthreads();

        // ---- GEMM2: h2 = silu(h1 @ W2 + b2); result overwrites H1 ----
        {
            u64 p0[4], p1[4];
            #pragma unroll
            for (int j = 0; j < 4; ++j) { p0[j] = 0ull; p1[j] = 0ull; }
            const int cb = 8 * w;
            #pragma unroll 4
            for (int k = 0; k < HIDv; ++k) {
                u64 A0 = splat2(sm[OH1 + k * TEP + lane]);
                u64 A1 = splat2(sm[OH1 + k * TEP + lane + 32]);
                const ulonglong2* wr = (const ulonglong2*)&sm[OW2 + k * HIDv + cb];
                ulonglong2 w0 = wr[0], w1 = wr[1];
                ffma2(p0[0], A0, w0.x); ffma2(p0[1], A0, w0.y);
                ffma2(p0[2], A0, w1.x); ffma2(p0[3], A0, w1.y);
                ffma2(p1[0], A1, w0.x); ffma2(p1[1], A1, w0.y);
                ffma2(p1[2], A1, w1.x); ffma2(p1[3], A1, w1.y);
            }
            __syncthreads();
            #pragma unroll
            for (int j = 0; j < 4; ++j) {
                float l0, h0, l1, h1;
                unpack2(p0[j], l0, h0); unpack2(p1[j], l1, h1);
                float ba = sm[OB2 + cb + 2*j], bbb = sm[OB2 + cb + 2*j + 1];
                sm[OH1 + (cb + 2*j)     * TEP + lane]      = silu_f(l0 + ba);
                sm[OH1 + (cb + 2*j + 1) * TEP + lane]      = silu_f(h0 + bbb);
                sm[OH1 + (cb + 2*j)     * TEP + lane + 32] = silu_f(l1 + ba);
                sm[OH1 + (cb + 2*j + 1) * TEP + lane + 32] = silu_f(h1 + bbb);
            }
        }
        __syncthreads();

        // ---- GEMM3 + gv/gr, coalesced scatter via smem transpose ----
        {
            u64 p0[8], p1[8];
            #pragma unroll
            for (int j = 0; j < 8; ++j) { p0[j] = 0ull; p1[j] = 0ull; }
            const int cb3 = 16 * w;
            #pragma unroll 2
            for (int k = 0; k < HIDv; ++k) {
                u64 A0 = splat2(sm[OH1 + k * TEP + lane]);
                u64 A1 = splat2(sm[OH1 + k * TEP + lane + 32]);
                const ulonglong2* wr = (const ulonglong2*)&sm[OW3 + k * M3P + cb3];
                ulonglong2 w0 = wr[0], w1 = wr[1], w2 = wr[2], w3 = wr[3];
                ffma2(p0[0], A0, w0.x); ffma2(p0[1], A0, w0.y);
                ffma2(p0[2], A0, w1.x); ffma2(p0[3], A0, w1.y);
                ffma2(p0[4], A0, w2.x); ffma2(p0[5], A0, w2.y);
                ffma2(p0[6], A0, w3.x); ffma2(p0[7], A0, w3.y);
                ffma2(p1[0], A1, w0.x); ffma2(p1[1], A1, w0.y);
                ffma2(p1[2], A1, w1.x); ffma2(p1[3], A1, w1.y);
                ffma2(p1[4], A1, w2.x); ffma2(p1[5], A1, w2.y);
                ffma2(p1[6], A1, w3.x); ffma2(p1[7], A1, w3.y);
            }

            if (w < 6) {
                float g0 = 0.0f, g1 = 0.0f;
                #pragma unroll 4
                for (int k = 0; k < HIDv; ++k) {
                    float ww = sm[OW3 + k * M3P + 128 + w];
                    g0 += sm[OH1 + k * TEP + lane] * ww;
                    g1 += sm[OH1 + k * TEP + lane + 32] * ww;
                }
                float bb = sm[OB3 + 128 + w];
                gvg[w * 64 + lane]      = g0 + bb;
                gvg[w * 64 + lane + 32] = g1 + bb;
            }

            float c0 = Cs[lane], c1 = Cs[lane + 32];
            float m0[16], m1[16];
            #pragma unroll
            for (int j = 0; j < 8; ++j) {
                unpack2(p0[j], m0[2*j], m0[2*j+1]);
                unpack2(p1[j], m1[2*j], m1[2*j+1]);
            }
            #pragma unroll
            for (int j = 0; j < 16; ++j) {
                float bb = sm[OB3 + cb3 + j];
                m0[j] = (m0[j] + bb) * c0;
                m1[j] = (m1[j] + bb) * c1;
            }
            __syncthreads();

            const int half0 = (w < 4) ? 0 : 1;
            const int cbh = cb3 - half0 * 64;

            #pragma unroll
            for (int half = 0; half < 2; ++half) {
                if (half0 == half) {
                    float4* t0 = (float4*)&sm[OH1 + lane * TRS + cbh];
                    float4* t1 = (float4*)&sm[OH1 + (lane + 32) * TRS + cbh];
                    t0[0] = make_float4(m0[0], m0[1], m0[2], m0[3]);
                    t0[1] = make_float4(m0[4], m0[5], m0[6], m0[7]);
                    t0[2] = make_float4(m0[8], m0[9], m0[10], m0[11]);
                    t0[3] = make_float4(m0[12], m0[13], m0[14], m0[15]);
                    t1[0] = make_float4(m1[0], m1[1], m1[2], m1[3]);
                    t1[1] = make_float4(m1[4], m1[5], m1[6], m1[7]);
                    t1[2] = make_float4(m1[8], m1[9], m1[10], m1[11]);
                    t1[3] = make_float4(m1[12], m1[13], m1[14], m1[15]);
                }
                __syncthreads();
                #pragma unroll
                for (int it = 0; it < 4; ++it) {
                    int e = w * 8 + it * 2 + (lane >> 4);
                    int c4 = (lane & 15) * 4;
                    float4 val = *(const float4*)&sm[OH1 + e * TRS + c4];
                    float* bp = &g_sagg[(size_t)dstS[e] * SDv + half * 64 + c4];
                    red4(bp, val.x, val.y, val.z, val.w);
                }
                __syncthreads();
            }
        }

        // vm scatter
        for (int idx = tid; idx < 9 * TILE; idx += NT) {
            int e = idx / 9;
            if (e >= ne) break;
            int c = idx - e * 9;
            int i3 = c / 3, j3 = c - i3 * 3;
            int se = srcS[e], de = dstS[e];
            float val = (g_v[(size_t)se * 9 + c] * gvg[i3 * 64 + e]
                       + rv[(size_t)(e0 + e) * 3 + j3] * gvg[(3 + i3) * 64 + e]) * Cs[e];
            atomicAdd(&g_vagg[(size_t)de * 9 + c], val);
        }
        __syncthreads();
    }
}

// -------------------- fused node kernel --------------------
__global__ void __launch_bounds__(NT, 1)
k_node(const float* __restrict__ Wn1g, const float* __restrict__ bn1g,
       const float* __restrict__ Wn2g, const float* __restrict__ bn2g,
       float* __restrict__ outp, int last, int l)
{
    extern __shared__ float sm[];
    const int tid = threadIdx.x;
    const int w = tid >> 5, lane = tid & 31;

    const float* Wn1 = Wn1g + (size_t)l * 2 * SDv * HIDv;
    const float* bn1 = bn1g + l * HIDv;
    const float* Wn2 = Wn2g + (size_t)l * HIDv * SDv;
    const float* bn2 = bn2g + l * SDv;

    for (int i = tid; i < 2 * SDv * HIDv; i += NT) sm[OWn1 + i] = Wn1[i];
    for (int i = tid; i < HIDv; i += NT) sm[OBn1 + i] = bn1[i];
    for (int i = tid; i < HIDv * SDv; i += NT) sm[OWn2 + i] = Wn2[i];
    for (int i = tid; i < SDv; i += NT) sm[OBn2 + i] = bn2[i];
    __syncthreads();

    float* out_s = outp;
    float* out_v = outp + (size_t)Nn * SDv;

    for (int tile = blockIdx.x; tile < NTILES_N; tile += gridDim.x) {
        const int n0 = tile * TILE;
        const int nn = min(TILE, Nn - n0);

        #pragma unroll 4
        for (int i = tid; i < TILE * SDv; i += NT) {
            int n = i >> 7, k = i & 127;
            float a = 0.0f, b = 0.0f;
            if (n < nn) {
                a = g_s[(size_t)(n0 + n) * SDv + k];
                b = g_sagg[(size_t)(n0 + n) * SDv + k];
            }
            sm[OX + k * TEP + n]         = a;
            sm[OX + (128 + k) * TEP + n] = b;
        }
        __syncthreads();

        // GEMM A: u = silu(x @ Wn1 + bn1), K=256
        {
            u64 p0[4], p1[4];
            #pragma unroll
            for (int j = 0; j < 4; ++j) { p0[j] = 0ull; p1[j] = 0ull; }
            const int cb = 8 * w;
            #pragma unroll 4
            for (int k = 0; k < 2 * SDv; ++k) {
                u64 A0 = splat2(sm[OX + k * TEP + lane]);
                u64 A1 = splat2(sm[OX + k * TEP + lane + 32]);
                const ulonglong2* wr = (const ulonglong2*)&sm[OWn1 + k * HIDv + cb];
                ulonglong2 w0 = wr[0], w1 = wr[1];
                ffma2(p0[0], A0, w0.x); ffma2(p0[1], A0, w0.y);
                ffma2(p0[2], A0, w1.x); ffma2(p0[3], A0, w1.y);
                ffma2(p1[0], A1, w0.x); ffma2(p1[1], A1, w0.y);
                ffma2(p1[2], A1, w1.x); ffma2(p1[3], A1, w1.y);
            }
            #pragma unroll
            for (int j = 0; j < 4; ++j) {
                float l0, h0, l1, h1;
                unpack2(p0[j], l0, h0); unpack2(p1[j], l1, h1);
                float ba = sm[OBn1 + cb + 2*j], bbb = sm[OBn1 + cb + 2*j + 1];
                sm[OU + (cb + 2*j)     * TEP + lane]      = silu_f(l0 + ba);
                sm[OU + (cb + 2*j + 1) * TEP + lane]      = silu_f(h0 + bbb);
                sm[OU + (cb + 2*j)     * TEP + lane + 32] = silu_f(l1 + ba);
                sm[OU + (cb + 2*j + 1) * TEP + lane + 32] = silu_f(h1 + bbb);
            }
        }
        __syncthreads();

        // GEMM B: s_new = s + u @ Wn2 + bn2
        {
            u64 p0[8], p1[8];
            #pragma unroll
            for (int j = 0; j < 8; ++j) { p0[j] = 0ull; p1[j] = 0ull; }
            const int cb3 = 16 * w;
            #pragma unroll 2
            for (int k = 0; k < HIDv; ++k) {
                u64 A0 = splat2(sm[OU + k * TEP + lane]);
                u64 A1 = splat2(sm[OU + k * TEP + lane + 32]);
                const ulonglong2* wr = (const ulonglong2*)&sm[OWn2 + k * SDv + cb3];
                ulonglong2 w0 = wr[0], w1 = wr[1], w2 = wr[2], w3 = wr[3];
                ffma2(p0[0], A0, w0.x); ffma2(p0[1], A0, w0.y);
                ffma2(p0[2], A0, w1.x); ffma2(p0[3], A0, w1.y);
                ffma2(p0[4], A0, w2.x); ffma2(p0[5], A0, w2.y);
                ffma2(p0[6], A0, w3.x); ffma2(p0[7], A0, w3.y);
                ffma2(p1[0], A1, w0.x); ffma2(p1[1], A1, w0.y);
                ffma2(p1[2], A1, w1.x); ffma2(p1[3], A1, w1.y);
                ffma2(p1[4], A1, w2.x); ffma2(p1[5], A1, w2.y);
                ffma2(p1[6], A1, w3.x); ffma2(p1[7], A1, w3.y);
            }
            float m0[16], m1[16];
            #pragma unroll
            for (int j = 0; j < 8; ++j) {
                unpack2(p0[j], m0[2*j], m0[2*j+1]);
                unpack2(p1[j], m1[2*j], m1[2*j+1]);
            }
            float* dst_s = last ? out_s : g_s;
            if (lane < nn) {
                float4* srow = (float4*)&dst_s[(size_t)(n0 + lane) * SDv + cb3];
                #pragma unroll
                for (int j4 = 0; j4 < 4; ++j4) {
                    float4 vv;
                    vv.x = sm[OX + (cb3 + 4*j4 + 0) * TEP + lane] + m0[4*j4 + 0] + sm[OBn2 + cb3 + 4*j4 + 0];
                    vv.y = sm[OX + (cb3 + 4*j4 + 1) * TEP + lane] + m0[4*j4 + 1] + sm[OBn2 + cb3 + 4*j4 + 1];
                    vv.z = sm[OX + (cb3 + 4*j4 + 2) * TEP + lane] + m0[4*j4 + 2] + sm[OBn2 + cb3 + 4*j4 + 2];
                    vv.w = sm[OX + (cb3 + 4*j4 + 3) * TEP + lane] + m0[4*j4 + 3] + sm[OBn2 + cb3 + 4*j4 + 3];
                    srow[j4] = vv;
                }
            }
            if (lane + 32 < nn) {
                float4* srow = (float4*)&dst_s[(size_t)(n0 + lane + 32) * SDv + cb3];
                #pragma unroll
                for (int j4 = 0; j4 < 4; ++j4) {
                    float4 vv;
                    vv.x = sm[OX + (cb3 + 4*j4 + 0) * TEP + lane + 32] + m1[4*j4 + 0] + sm[OBn2 + cb3 + 4*j4 + 0];
                    vv.y = sm[OX + (cb3 + 4*j4 + 1) * TEP + lane + 32] + m1[4*j4 + 1] + sm[OBn2 + cb3 + 4*j4 + 1];
                    vv.z = sm[OX + (cb3 + 4*j4 + 2) * TEP + lane + 32] + m1[4*j4 + 2] + sm[OBn2 + cb3 + 4*j4 + 2];
                    vv.w = sm[OX + (cb3 + 4*j4 + 3) * TEP + lane + 32] + m1[4*j4 + 3] + sm[OBn2 + cb3 + 4*j4 + 3];
                    srow[j4] = vv;
                }
            }
        }

        // v update
        for (int idx = tid; idx < 9 * TILE; idx += NT) {
            int nl = idx / 9;
            if (nl >= nn) break;
            int c = idx - nl * 9;
            int n = n0 + nl;
            float nv = g_v[(size_t)n * 9 + c] + g_vagg[(size_t)n * 9 + c] * g_inv[n];
            if (last) out_v[(size_t)n * 9 + c] = nv;
            else      g_v[(size_t)n * 9 + c] = nv;
        }
        __syncthreads();
    }
}

// -------------------- launch --------------------
extern "C" void kernel_launch(void* const* d_in, const int* in_sizes, int n_in,
                              void* d_out, int out_size)
{
    const float* s   = (const float*)d_in[0];
    const float* v   = (const float*)d_in[1];
    const int*   ei  = (const int*)d_in[2];
    const float* dv  = (const float*)d_in[3];
    const float* rv  = (const float*)d_in[4];
    const float* W1  = (const float*)d_in[5];
    const float* b1  = (const float*)d_in[6];
    const float* W2  = (const float*)d_in[7];
    const float* b2  = (const float*)d_in[8];
    const float* W3  = (const float*)d_in[9];
    const float* b3  = (const float*)d_in[10];
    const float* Wn1 = (const float*)d_in[11];
    const float* bn1 = (const float*)d_in[12];
    const float* Wn2 = (const float*)d_in[13];
    const float* bn2 = (const float*)d_in[14];
    const int* dst = ei;
    const int* src = ei + Ee;
    float* outp = (float*)d_out;

    cudaFuncSetAttribute(k_edge, cudaFuncAttributeMaxDynamicSharedMemorySize, SME_BYTES);
    cudaFuncSetAttribute(k_pq,   cudaFuncAttributeMaxDynamicSharedMemorySize, SMP_BYTES);
    cudaFuncSetAttribute(k_node, cudaFuncAttributeMaxDynamicSharedMemorySize, SMN_BYTES);

    // order arranged so k_edge is launch #4 (ncu capture slot)
    k_init<<<(Nn * SDv + 255) / 256, 256>>>(s, v);
    k_pq<<<296, NT, SMP_BYTES>>>(W1, 0);
    k_count<<<(Ee + 255) / 256, 256>>>(dst);
    k_edge<<<444, NT, SME_BYTES>>>(dst, src, dv, rv, W1, b1, W2, b2, W3, b3, 0);
    k_inv<<<(Nn + 255) / 256, 256>>>();
    k_node<<<148, NT, SMN_BYTES>>>(Wn1, bn1, Wn2, bn2, outp, 0, 0);

    for (int l = 1; l < 4; ++l) {
        k_pq<<<296, NT, SMP_BYTES>>>(W1, l);
        k_edge<<<444, NT, SME_BYTES>>>(dst, src, dv, rv, W1, b1, W2, b2, W3, b3, l);
        k_node<<<148, NT, SMN_BYTES>>>(Wn1, bn1, Wn2, bn2, outp, (l == 3) ? 1 : 0, l);
    }
}